// round 16
// baseline (speedup 1.0000x reference)
#include <cuda_runtime.h>
#include <cuda_bf16.h>
#include <cuda_fp16.h>
#include <cstdint>
#include <cmath>

#define NPTS 8192
#define DIM  512
#define NBLK 64
#define QS   23.0f
#define QINV (1.0f / 23.0f)
#define CCOEF (2.0f / (23.0f * 23.0f))

// ---------------- device scratch (no allocations allowed) ----------------
__device__ float g_sq[NPTS];
__device__ float g_e2[NPTS];
__device__ int   g_S2maxBits;  // idempotent atomicMax across replays
__device__ int   g_E2maxBits;
__device__ int   g_closest[NPTS];
__device__ signed char g_xq[(size_t)NPTS * 512];        // int8 quantized x
__device__ __half g_c[(size_t)NPTS * NPTS];             // filter distances (fp16)
__device__ float g_Z1[NPTS * 64];
__device__ float g_Z2[NPTS * 32];
__device__ float g_h2[NPTS * 64];

// ---------------- helpers ----------------
typedef unsigned long long u64;
__device__ __forceinline__ uint32_t smem_u32(const void* p) {
    uint32_t a;
    asm("{ .reg .u64 t; cvta.to.shared.u64 t, %1; cvt.u32.u64 %0, t; }" : "=r"(a) : "l"(p));
    return a;
}
#define SWZ(b) ((b) ^ (((b) >> 3) & 0x70))

__device__ __forceinline__ void cp_async16(uint32_t dst, const void* src) {
    asm volatile("cp.async.cg.shared.global [%0], [%1], 16;" :: "r"(dst), "l"(src));
}
__device__ __forceinline__ void ldmatrix_x4(uint32_t* r, uint32_t addr) {
    asm volatile("ldmatrix.sync.aligned.m8n8.x4.shared.b16 {%0,%1,%2,%3}, [%4];"
                 : "=r"(r[0]), "=r"(r[1]), "=r"(r[2]), "=r"(r[3]) : "r"(addr));
}
__device__ __forceinline__ void mma16832_s8(int* d, const uint32_t* a, uint32_t b0, uint32_t b1) {
    asm volatile(
        "mma.sync.aligned.m16n8k32.row.col.s32.s8.s8.s32 "
        "{%0,%1,%2,%3}, {%4,%5,%6,%7}, {%8,%9}, {%0,%1,%2,%3};"
        : "+r"(d[0]), "+r"(d[1]), "+r"(d[2]), "+r"(d[3])
        : "r"(a[0]), "r"(a[1]), "r"(a[2]), "r"(a[3]), "r"(b0), "r"(b1));
}
__device__ __forceinline__ u64 pack2(float x, float y) {
    u64 r;
    asm("mov.b64 %0, {%1, %2};" : "=l"(r) : "r"(__float_as_uint(x)), "r"(__float_as_uint(y)));
    return r;
}
__device__ __forceinline__ u64 fma2(u64 a, u64 b, u64 c) {
    u64 d;
    asm("fma.rn.f32x2 %0, %1, %2, %3;" : "=l"(d) : "l"(a), "l"(b), "l"(c));
    return d;
}
__device__ __forceinline__ float2 unpack2(u64 p) {
    unsigned lo, hi;
    asm("mov.b64 {%0, %1}, %2;" : "=r"(lo), "=r"(hi) : "l"(p));
    float2 f;
    f.x = __uint_as_float(lo);
    f.y = __uint_as_float(hi);
    return f;
}

// ---------------- kernel 0: quantize + norms + error norms (fused) ----------------
__global__ __launch_bounds__(256, 4) void convert_norms_kernel(const float* __restrict__ xs) {
    int warp = threadIdx.x >> 5, lane = threadIdx.x & 31;
    int row = blockIdx.x * 8 + warp;
    const float* p = xs + (size_t)row * DIM;
    float sq = 0.f, e2s = 0.f;
#pragma unroll
    for (int t = 0; t < 16; t++) {
        float x = p[lane + 32 * t];
        int q = __float2int_rn(x * QS);
        q = min(max(q, -127), 127);
        g_xq[(size_t)row * 512 + lane + 32 * t] = (signed char)q;
        float e = x - (float)q * QINV;
        sq += x * x;
        e2s += e * e;
    }
#pragma unroll
    for (int off = 16; off; off >>= 1) {
        sq  += __shfl_xor_sync(0xffffffffu, sq, off);
        e2s += __shfl_xor_sync(0xffffffffu, e2s, off);
    }
    if (lane == 0) {
        g_sq[row] = sq;
        float s2 = sqrtf(sq), e2 = sqrtf(e2s);
        g_e2[row] = e2;
        atomicMax(&g_S2maxBits, __float_as_int(s2));
        atomicMax(&g_E2maxBits, __float_as_int(e2));
    }
}

// ---------------- kernel 1: triangular IMMA gram (int8, K=512) ----------------
// CTA 128x128 over block pairs (I<=J). 4 K-chunks of 128 int8 (128 B rows,
// one SW128 atom), 3-stage cp.async ring, mma.m16n8k32.s8 (s32 accum exact).
// fp16 epilogue: c = sq_j - 2*acc/s^2 - 1024, direct + smem-transposed stores,
// diagonal poisoned inline.
#define TM 128
#define TN 128
#define NCHUNK 4
#define NS 3
#define A_BYTES (TM * 128)
#define B_BYTES (TN * 128)
#define STAGE_BYTES (A_BYTES + B_BYTES)
#define SM_SQC 0
#define SM_SQR 512
#define SM_TILE0 1024
#define SMEM_GEMM (SM_TILE0 + NS * STAGE_BYTES)
#define TRANS_STRIDE 136

__device__ __forceinline__ int tri_cum(int I) { return 64 * I - (I * (I - 1)) / 2; }

__global__ __launch_bounds__(256, 2) void gram_store_tri() {
    extern __shared__ char smem[];
    const uint32_t sb = smem_u32(smem);
    float* sSqC = (float*)(smem + SM_SQC);
    float* sSqR = (float*)(smem + SM_SQR);

    const int tid = threadIdx.x;
    const int lane = tid & 31, wid = tid >> 5;
    const int warp_m = wid & 3, warp_n = wid >> 2;   // 4 x 2

    const int t = blockIdx.x;
    int I = (int)((129.0 - sqrt(129.0 * 129.0 - 8.0 * (double)t)) * 0.5);
    while (tri_cum(I + 1) <= t) I++;
    while (tri_cum(I) > t) I--;
    const int J = I + (t - tri_cum(I));
    const int row0 = I * TM;
    const int col0 = J * TN;
    const bool diag = (I == J);

    if (tid < 128) {
        sSqC[tid] = g_sq[col0 + tid];
        sSqR[tid] = g_sq[row0 + tid];
    }

    int acc[2][8][4];
#pragma unroll
    for (int mf = 0; mf < 2; mf++)
#pragma unroll
        for (int nf = 0; nf < 8; nf++)
#pragma unroll
            for (int e = 0; e < 4; e++) acc[mf][nf][e] = 0;

    const int lm_r = lane & 15;
    const int lm_kb = (lane >> 4) * 16;   // byte offset within 32B kstep

    const signed char* gXr = g_xq + (size_t)row0 * 512;
    const signed char* gXc = g_xq + (size_t)col0 * 512;

#define STAGE_CHUNK(cc)                                                                 \
    do {                                                                                \
        const int _st = (cc) % NS;                                                      \
        const uint32_t _sa = sb + SM_TILE0 + _st * STAGE_BYTES;                         \
        const uint32_t _sb2 = _sa + A_BYTES;                                            \
        const signed char* _gA = gXr + (cc) * 128;                                      \
        const signed char* _gB = gXc + (cc) * 128;                                      \
        _Pragma("unroll")                                                               \
        for (int _it = 0; _it < 4; _it++) {                                             \
            int _e = tid + _it * 256, _r = _e >> 3, _s = _e & 7;                        \
            cp_async16(_sa + SWZ(_r * 128 + _s * 16), _gA + (size_t)_r * 512 + _s * 16);\
            cp_async16(_sb2 + SWZ(_r * 128 + _s * 16), _gB + (size_t)_r * 512 + _s * 16);\
        }                                                                               \
        asm volatile("cp.async.commit_group;");                                         \
    } while (0)

    STAGE_CHUNK(0);
    STAGE_CHUNK(1);

    for (int c = 0; c < NCHUNK; c++) {
        if (c + 1 < NCHUNK) asm volatile("cp.async.wait_group 1;");
        else                asm volatile("cp.async.wait_group 0;");
        __syncthreads();
        if (c + 2 < NCHUNK) STAGE_CHUNK(c + 2);

        const uint32_t Ab = sb + SM_TILE0 + (c % NS) * STAGE_BYTES;
        const uint32_t Bb = Ab + A_BYTES;
#pragma unroll
        for (int ks = 0; ks < 4; ks++) {   // K=32 int8 per step
            const int kb = ks * 32;
            uint32_t a[2][4];
#pragma unroll
            for (int mf = 0; mf < 2; mf++) {
                int r = warp_m * 32 + mf * 16 + lm_r;
                ldmatrix_x4(a[mf], Ab + SWZ(r * 128 + kb + lm_kb));
            }
            uint32_t b[4][4];
#pragma unroll
            for (int p = 0; p < 4; p++) {
                int n = warp_n * 64 + p * 16 + lm_r;
                ldmatrix_x4(b[p], Bb + SWZ(n * 128 + kb + lm_kb));
            }
#pragma unroll
            for (int mf = 0; mf < 2; mf++)
#pragma unroll
                for (int nf = 0; nf < 8; nf++)
                    mma16832_s8(acc[mf][nf], a[mf], b[nf >> 1][nf & 1], b[nf >> 1][(nf & 1) + 2]);
        }
    }

    __syncthreads();  // LDSM done; stage smem reusable for transpose
    __half* trans = (__half*)(smem + SM_TILE0);

#pragma unroll
    for (int mf = 0; mf < 2; mf++) {
        const int ra = warp_m * 32 + mf * 16 + (lane >> 2);
        const int rb = ra + 8;
        const float sqa = sSqR[ra] - 1024.f, sqb = sSqR[rb] - 1024.f;
#pragma unroll
        for (int nf = 0; nf < 8; nf++) {
            const int lc = warp_n * 64 + nf * 8 + (lane & 3) * 2;
            const float sc0 = sSqC[lc] - 1024.f, sc1 = sSqC[lc + 1] - 1024.f;
            float d0 = (float)acc[mf][nf][0];
            float d1 = (float)acc[mf][nf][1];
            float d2 = (float)acc[mf][nf][2];
            float d3 = (float)acc[mf][nf][3];
            float c00 = fmaf(d0, -CCOEF, sc0);
            float c01 = fmaf(d1, -CCOEF, sc1);
            float c10 = fmaf(d2, -CCOEF, sc0);
            float c11 = fmaf(d3, -CCOEF, sc1);
            if (diag) {  // uniform branch: only 64/2080 CTAs
                const int gra = row0 + ra, grb = row0 + rb;
                const int c0 = col0 + lc;
                if (c0 == gra)     c00 = 60000.f;
                if (c0 + 1 == gra) c01 = 60000.f;
                if (c0 == grb)     c10 = 60000.f;
                if (c0 + 1 == grb) c11 = 60000.f;
            }
            *(__half2*)&g_c[(size_t)(row0 + ra) * NPTS + col0 + lc] = __floats2half2_rn(c00, c01);
            *(__half2*)&g_c[(size_t)(row0 + rb) * NPTS + col0 + lc] = __floats2half2_rn(c10, c11);
            if (!diag) {
                trans[lc * TRANS_STRIDE + ra]       = __float2half_rn(fmaf(d0, -CCOEF, sqa));
                trans[(lc + 1) * TRANS_STRIDE + ra] = __float2half_rn(fmaf(d1, -CCOEF, sqa));
                trans[lc * TRANS_STRIDE + rb]       = __float2half_rn(fmaf(d2, -CCOEF, sqb));
                trans[(lc + 1) * TRANS_STRIDE + rb] = __float2half_rn(fmaf(d3, -CCOEF, sqb));
            }
        }
    }
    if (!diag) {
        __syncthreads();
#pragma unroll
        for (int it = 0; it < 8; it++) {
            int e = tid + it * 256;
            int r = e >> 4, s = e & 15;
            ((uint4*)(g_c + (size_t)(col0 + r) * NPTS + row0))[s] =
                ((const uint4*)(trans + r * TRANS_STRIDE))[s];
        }
    }
}

// ---------------- kernel 2: smem-cached scan + exact recheck ----------------
__global__ __launch_bounds__(256, 4) void scan_kernel(const float* __restrict__ xs) {
    __shared__ uint32_t sRow[4096];   // 16 KB: full fp16 row
    __shared__ float sX[512];
    __shared__ float wMin[8];
    __shared__ float wBD[8];
    __shared__ int   wBJ[8];
    __shared__ int   qbuf[2048];
    __shared__ int   qn;
    const int row = blockIdx.x;
    const int tid = threadIdx.x, lane = tid & 31, wid = tid >> 5;
    const uint4* crow = (const uint4*)(g_c + (size_t)row * NPTS);

    if (tid == 0) qn = 0;
    for (int i = tid; i < 512; i += 256) sX[i] = xs[(size_t)row * DIM + i];

    // pass 1: row -> smem, packed half2 min on the fly
    __half2 mn2 = __floats2half2_rn(60000.f, 60000.f);
#pragma unroll
    for (int it = 0; it < 4; it++) {
        uint4 v = crow[tid + it * 256];
        ((uint4*)sRow)[tid + it * 256] = v;
        mn2 = __hmin2(mn2, *(__half2*)&v.x);
        mn2 = __hmin2(mn2, *(__half2*)&v.y);
        mn2 = __hmin2(mn2, *(__half2*)&v.z);
        mn2 = __hmin2(mn2, *(__half2*)&v.w);
    }
    float m = fminf(__low2float(mn2), __high2float(mn2));
#pragma unroll
    for (int off = 16; off; off >>= 1) m = fminf(m, __shfl_xor_sync(0xffffffffu, m, off));
    if (lane == 0) wMin[wid] = m;
    __syncthreads();
    m = wMin[0];
#pragma unroll
    for (int w = 1; w < 8; w++) m = fminf(m, wMin[w]);

    // deterministic window: |c_err| <= 2(S2_i*E2max + E2_i*(S2max+E2max))
    const float S2max = __int_as_float(g_S2maxBits);
    const float E2max = __int_as_float(g_E2maxBits);
    const float sqi = g_sq[row];
    const float e2i = g_e2[row];
    const float bnd = 2.f * (sqrtf(sqi) * E2max + e2i * (S2max + E2max));
    const float th = m + 2.f * bnd + 1.5f;
    const __half2 th2 = __floats2half2_rn(th, th);

    // pass 2: candidate enumeration from smem
#pragma unroll 4
    for (int it = 0; it < 16; it++) {
        int w = tid + it * 256;
        __half2 x = *(__half2*)&sRow[w];
        __half2 lt = __hlt2(x, th2);
        if (__low2float(lt) != 0.f) {
            int s = atomicAdd(&qn, 1);
            if (s < 2048) qbuf[s] = 2 * w;
        }
        if (__high2float(lt) != 0.f) {
            int s = atomicAdd(&qn, 1);
            if (s < 2048) qbuf[s] = 2 * w + 1;
        }
    }
    __syncthreads();

    float bd = 1e30f;
    int bj = NPTS;
    const int nq = (qn < 2048) ? qn : 2048;
    for (int q0 = wid; q0 < nq; q0 += 8) {
        int j = qbuf[q0];
        const float* xj = xs + (size_t)j * DIM;
        float s = 0.f;
#pragma unroll
        for (int tt = 0; tt < 16; tt++) s += sX[lane + 32 * tt] * xj[lane + 32 * tt];
#pragma unroll
        for (int off = 16; off; off >>= 1) s += __shfl_xor_sync(0xffffffffu, s, off);
        float d = sqi + g_sq[j] - 2.f * s;
        if (d < bd || (d == bd && j < bj)) { bd = d; bj = j; }
    }

    if (lane == 0) { wBD[wid] = bd; wBJ[wid] = bj; }
    __syncthreads();
    if (tid == 0) {
        float fb = wBD[0]; int fj = wBJ[0];
#pragma unroll
        for (int w = 1; w < 8; w++) {
            if (wBD[w] < fb || (wBD[w] == fb && wBJ[w] < fj)) { fb = wBD[w]; fj = wBJ[w]; }
        }
        g_closest[row] = fj;
    }
}

// ---------------- kernel Z1: Z1 = xs @ W1^T + b1  (64x64 tiles, f32x2) ----------------
__global__ __launch_bounds__(256, 2) void z1_gemm(
    const float* __restrict__ xs, const float* __restrict__ W1,
    const float* __restrict__ b1) {
    __shared__ float As[64][68];
    __shared__ float Bs[64][68];
    const int tid = threadIdx.x;
    const int tx = tid & 15, ty = tid >> 4;
    const int row0 = blockIdx.x * 64;

    u64 acc2[4][2];
#pragma unroll
    for (int m = 0; m < 4; m++) { acc2[m][0] = 0ull; acc2[m][1] = 0ull; }

    for (int kb = 0; kb < DIM; kb += 64) {
#pragma unroll
        for (int l = 0; l < 4; l++) {
            int e = tid + l * 256;
            int r = e >> 4, k4 = (e & 15) * 4;
            float4 va = *(const float4*)&xs[(size_t)(row0 + r) * DIM + kb + k4];
            As[k4 + 0][r] = va.x; As[k4 + 1][r] = va.y; As[k4 + 2][r] = va.z; As[k4 + 3][r] = va.w;
            float4 vb = *(const float4*)&W1[(size_t)r * DIM + kb + k4];
            Bs[k4 + 0][r] = vb.x; Bs[k4 + 1][r] = vb.y; Bs[k4 + 2][r] = vb.z; Bs[k4 + 3][r] = vb.w;
        }
        __syncthreads();
#pragma unroll
        for (int k = 0; k < 64; k++) {
            float4 a = *(const float4*)&As[k][tx * 4];
            const u64* bp = (const u64*)&Bs[k][ty * 4];
            u64 b0 = bp[0], b1v = bp[1];
            float ar[4] = {a.x, a.y, a.z, a.w};
#pragma unroll
            for (int m = 0; m < 4; m++) {
                u64 a2 = pack2(ar[m], ar[m]);
                acc2[m][0] = fma2(a2, b0, acc2[m][0]);
                acc2[m][1] = fma2(a2, b1v, acc2[m][1]);
            }
        }
        __syncthreads();
    }
#pragma unroll
    for (int m = 0; m < 4; m++)
#pragma unroll
        for (int n2 = 0; n2 < 2; n2++) {
            float2 v = unpack2(acc2[m][n2]);
            int o = ty * 4 + n2 * 2;
            g_Z1[(size_t)(row0 + tx * 4 + m) * 64 + o]     = v.x + __ldg(&b1[o]);
            g_Z1[(size_t)(row0 + tx * 4 + m) * 64 + o + 1] = v.y + __ldg(&b1[o + 1]);
        }
}

// ---------------- kernel Z2: Z2 = W2 @ relu(Z1) + b2 ----------------
__global__ __launch_bounds__(256, 4) void z2_kernel(
    const float* __restrict__ W2, const float* __restrict__ b2) {
    __shared__ float sW2t[64 * 32];
    __shared__ float sA[8][64];
    const int tid = threadIdx.x;
    for (int i = tid; i < 32 * 64; i += 256) {
        int o = i >> 6, k = i & 63;
        sW2t[k * 32 + o] = W2[i];
    }
    __syncthreads();
    const int warp = tid >> 5, lane = tid & 31;
    const int row = blockIdx.x * 8 + warp;
    float* a1 = sA[warp];
    a1[lane] = fmaxf(g_Z1[(size_t)row * 64 + lane], 0.f);
    a1[lane + 32] = fmaxf(g_Z1[(size_t)row * 64 + lane + 32], 0.f);
    __syncwarp();
    float z = __ldg(&b2[lane]);
#pragma unroll
    for (int k = 0; k < 64; k++) z += sW2t[k * 32 + lane] * a1[k];
    g_Z2[(size_t)row * 32 + lane] = z;
}

// ---------------- kernel PAIR: masked JVP encoder + decoder front ----------------
__global__ __launch_bounds__(256, 4) void pair_kernel(
    const float* __restrict__ W2, const float* __restrict__ b2,
    const float* __restrict__ W3, const float* __restrict__ b3,
    const float* __restrict__ D1, const float* __restrict__ d1,
    const float* __restrict__ D2, const float* __restrict__ d2,
    float* __restrict__ out) {
    __shared__ float sW2t[64 * 32];
    __shared__ float sW3t[32 * 32];
    __shared__ float sD1t[32 * 32];
    __shared__ float sD2t[32 * 64];
    __shared__ float sScr[8][160];
    const int tid = threadIdx.x;
    for (int i = tid; i < 32 * 64; i += 256) { int o = i >> 6, k = i & 63; sW2t[k * 32 + o] = W2[i]; }
    for (int i = tid; i < 32 * 32; i += 256) { int o = i >> 5, k = i & 31; sW3t[k * 32 + o] = W3[i]; sD1t[k * 32 + o] = D1[i]; }
    for (int i = tid; i < 64 * 32; i += 256) { int o = i >> 5, k = i & 31; sD2t[k * 64 + o] = D2[i]; }
    __syncthreads();

    const int warp = tid >> 5, lane = tid & 31;
    const int row = blockIdx.x * 8 + warp;
    float* sU  = sScr[warp];
    float* sU2 = sU + 64;
    float* sZ  = sU + 96;
    float* sH1 = sU + 128;

    const int j = g_closest[row];
#pragma unroll
    for (int h = 0; h < 2; h++) {
        int k = lane + 32 * h;
        float zi = g_Z1[(size_t)row * 64 + k];
        float zj = g_Z1[(size_t)j * 64 + k];
        sU[k] = (zj > 0.f) ? zi : 0.f;
    }
    __syncwarp();
    {
        float u2 = __ldg(&b2[lane]);
#pragma unroll
        for (int k = 0; k < 64; k++) u2 += sW2t[k * 32 + lane] * sU[k];
        float z2j = g_Z2[(size_t)j * 32 + lane];
        sU2[lane] = (z2j > 0.f) ? u2 : 0.f;
    }
    __syncwarp();
    {
        float z = __ldg(&b3[lane]);
#pragma unroll
        for (int k = 0; k < 32; k++) z += sW3t[k * 32 + lane] * sU2[k];
        sZ[lane] = z;
        out[(size_t)NPTS * DIM + (size_t)row * 32 + lane] = z;
    }
    __syncwarp();
    {
        float h = __ldg(&d1[lane]);
#pragma unroll
        for (int k = 0; k < 32; k++) h += sD1t[k * 32 + lane] * sZ[k];
        sH1[lane] = fmaxf(h, 0.f);
    }
    __syncwarp();
#pragma unroll
    for (int hh = 0; hh < 2; hh++) {
        int o = lane + 32 * hh;
        float h = __ldg(&d2[o]);
#pragma unroll
        for (int k = 0; k < 32; k++) h += sD2t[k * 64 + o] * sH1[k];
        g_h2[(size_t)row * 64 + o] = fmaxf(h, 0.f);
    }
}

// ---------------- kernel DEC: x_hat = h2 @ D3^T + d3  (f32x2 inner) ----------------
#define DEC_SMEM (2 * 64 * 132 * 4)
__global__ __launch_bounds__(256, 2) void dec_gemm(
    const float* __restrict__ D3, const float* __restrict__ d3,
    float* __restrict__ out) {
    extern __shared__ float ds[];
    float (*As)[132] = (float(*)[132])ds;
    float (*Bs)[132] = (float(*)[132])(ds + 64 * 132);
    const int tid = threadIdx.x;
    const int tx = tid & 15, ty = tid >> 4;
    const int row0 = blockIdx.x * 128;
    const int col0 = blockIdx.y * 128;

#pragma unroll
    for (int l = 0; l < 8; l++) {
        int e = tid + l * 256;
        int r = e >> 4, k4 = (e & 15) * 4;
        float4 va = *(const float4*)&g_h2[(size_t)(row0 + r) * 64 + k4];
        As[k4 + 0][r] = va.x; As[k4 + 1][r] = va.y; As[k4 + 2][r] = va.z; As[k4 + 3][r] = va.w;
        float4 vb = *(const float4*)&D3[(size_t)(col0 + r) * 64 + k4];
        Bs[k4 + 0][r] = vb.x; Bs[k4 + 1][r] = vb.y; Bs[k4 + 2][r] = vb.z; Bs[k4 + 3][r] = vb.w;
    }
    __syncthreads();

    u64 acc2[8][4];
#pragma unroll
    for (int m = 0; m < 8; m++)
#pragma unroll
        for (int n2 = 0; n2 < 4; n2++) acc2[m][n2] = 0ull;

#pragma unroll
    for (int k = 0; k < 64; k++) {
        float ar[8];
        float4 a0 = *(const float4*)&As[k][tx * 8];
        float4 a1 = *(const float4*)&As[k][tx * 8 + 4];
        ar[0] = a0.x; ar[1] = a0.y; ar[2] = a0.z; ar[3] = a0.w;
        ar[4] = a1.x; ar[5] = a1.y; ar[6] = a1.z; ar[7] = a1.w;
        const u64* bp = (const u64*)&Bs[k][ty * 8];
        u64 b2[4] = {bp[0], bp[1], bp[2], bp[3]};
#pragma unroll
        for (int m = 0; m < 8; m++) {
            u64 a2 = pack2(ar[m], ar[m]);
#pragma unroll
            for (int n2 = 0; n2 < 4; n2++) acc2[m][n2] = fma2(a2, b2[n2], acc2[m][n2]);
        }
    }

#pragma unroll
    for (int m = 0; m < 8; m++) {
        int r = row0 + tx * 8 + m;
#pragma unroll
        for (int n2 = 0; n2 < 4; n2++) {
            float2 v = unpack2(acc2[m][n2]);
            int cc = col0 + ty * 8 + n2 * 2;
            out[(size_t)r * DIM + cc]     = v.x + __ldg(&d3[cc]);
            out[(size_t)r * DIM + cc + 1] = v.y + __ldg(&d3[cc + 1]);
        }
    }
}

// ---------------- launch ----------------
extern "C" void kernel_launch(void* const* d_in, const int* in_sizes, int n_in,
                              void* d_out, int out_size) {
    const float* xs = (const float*)d_in[0];
    const float* W1 = (const float*)d_in[1];
    const float* b1 = (const float*)d_in[2];
    const float* W2 = (const float*)d_in[3];
    const float* b2 = (const float*)d_in[4];
    const float* W3 = (const float*)d_in[5];
    const float* b3 = (const float*)d_in[6];
    const float* D1 = (const float*)d_in[7];
    const float* d1 = (const float*)d_in[8];
    const float* D2 = (const float*)d_in[9];
    const float* d2 = (const float*)d_in[10];
    const float* D3 = (const float*)d_in[11];
    const float* d3 = (const float*)d_in[12];
    float* out = (float*)d_out;

    static cudaStream_t s_z = nullptr;
    static cudaEvent_t ev_g = nullptr, ev_z = nullptr;
    if (s_z == nullptr) {
        cudaStreamCreateWithFlags(&s_z, cudaStreamNonBlocking);
        cudaEventCreateWithFlags(&ev_g, cudaEventDisableTiming);
        cudaEventCreateWithFlags(&ev_z, cudaEventDisableTiming);
    }

    convert_norms_kernel<<<NPTS / 8, 256>>>(xs);

    cudaFuncSetAttribute(gram_store_tri, cudaFuncAttributeMaxDynamicSharedMemorySize, SMEM_GEMM);
    const int npairs = NBLK * (NBLK + 1) / 2;  // 2080
    gram_store_tri<<<npairs, 256, SMEM_GEMM>>>();
    cudaEventRecord(ev_g, 0);

    // z-path overlaps with the (memory-bound) scan, not the tensor-bound gram
    cudaStreamWaitEvent(s_z, ev_g, 0);
    z1_gemm<<<NPTS / 64, 256, 0, s_z>>>(xs, W1, b1);
    z2_kernel<<<NPTS / 8, 256, 0, s_z>>>(W2, b2);
    cudaEventRecord(ev_z, s_z);

    scan_kernel<<<NPTS, 256>>>(xs);

    cudaStreamWaitEvent(0, ev_z, 0);
    pair_kernel<<<NPTS / 8, 256>>>(W2, b2, W3, b3, D1, d1, D2, d2, out);

    cudaFuncSetAttribute(dec_gemm, cudaFuncAttributeMaxDynamicSharedMemorySize, DEC_SMEM);
    dim3 gdec(NPTS / 128, 4);
    dec_gemm<<<gdec, 256, DEC_SMEM>>>(D3, d3, out);
}

// round 17
// speedup vs baseline: 1.5884x; 1.5884x over previous
#include <cuda_runtime.h>
#include <cuda_bf16.h>
#include <cuda_fp16.h>
#include <cstdint>
#include <cmath>

#define NPTS 8192
#define DIM  512
#define NBLK 64

// ---------------- device scratch (no allocations allowed) ----------------
__device__ float g_sq[NPTS];
__device__ float g_hin[NPTS];
__device__ float g_lon[NPTS];
__device__ int   g_HmaxBits;   // idempotent atomicMax across replays
__device__ int   g_LmaxBits;
__device__ int   g_closest[NPTS];
__device__ __nv_bfloat16 g_xb[(size_t)NPTS * 512];      // hi(bf16) per row
__device__ __half g_c[(size_t)NPTS * NPTS];             // filtered distances (fp16)
__device__ float g_Z1[NPTS * 64];
__device__ float g_Z2[NPTS * 32];
__device__ float g_h2[NPTS * 64];

// ---------------- helpers ----------------
typedef unsigned long long u64;
__device__ __forceinline__ uint32_t smem_u32(const void* p) {
    uint32_t a;
    asm("{ .reg .u64 t; cvta.to.shared.u64 t, %1; cvt.u32.u64 %0, t; }" : "=r"(a) : "l"(p));
    return a;
}
#define SWZ(b) ((b) ^ (((b) >> 3) & 0x70))

__device__ __forceinline__ void cp_async16(uint32_t dst, const void* src) {
    asm volatile("cp.async.cg.shared.global [%0], [%1], 16;" :: "r"(dst), "l"(src));
}
__device__ __forceinline__ void ldmatrix_x4(uint32_t* r, uint32_t addr) {
    asm volatile("ldmatrix.sync.aligned.m8n8.x4.shared.b16 {%0,%1,%2,%3}, [%4];"
                 : "=r"(r[0]), "=r"(r[1]), "=r"(r[2]), "=r"(r[3]) : "r"(addr));
}
__device__ __forceinline__ void mma16816(float* d, const uint32_t* a, uint32_t b0, uint32_t b1) {
    asm volatile(
        "mma.sync.aligned.m16n8k16.row.col.f32.bf16.bf16.f32 "
        "{%0,%1,%2,%3}, {%4,%5,%6,%7}, {%8,%9}, {%0,%1,%2,%3};"
        : "+f"(d[0]), "+f"(d[1]), "+f"(d[2]), "+f"(d[3])
        : "r"(a[0]), "r"(a[1]), "r"(a[2]), "r"(a[3]), "r"(b0), "r"(b1));
}
__device__ __forceinline__ u64 pack2(float x, float y) {
    u64 r;
    asm("mov.b64 %0, {%1, %2};" : "=l"(r) : "r"(__float_as_uint(x)), "r"(__float_as_uint(y)));
    return r;
}
__device__ __forceinline__ u64 fma2(u64 a, u64 b, u64 c) {
    u64 d;
    asm("fma.rn.f32x2 %0, %1, %2, %3;" : "=l"(d) : "l"(a), "l"(b), "l"(c));
    return d;
}
__device__ __forceinline__ float2 unpack2(u64 p) {
    unsigned lo, hi;
    asm("mov.b64 {%0, %1}, %2;" : "=r"(lo), "=r"(hi) : "l"(p));
    float2 f;
    f.x = __uint_as_float(lo);
    f.y = __uint_as_float(hi);
    return f;
}

// ---------------- kernel 0: convert + norms (fused) ----------------
__global__ __launch_bounds__(256, 8) void convert_norms_kernel(const float* __restrict__ xs) {
    int warp = threadIdx.x >> 5, lane = threadIdx.x & 31;
    int row = blockIdx.x * 8 + warp;
    const float* p = xs + (size_t)row * DIM;
    float sq = 0.f, h2s = 0.f, l2s = 0.f;
#pragma unroll
    for (int t = 0; t < 16; t++) {
        float x = p[lane + 32 * t];
        __nv_bfloat16 hb = __float2bfloat16(x);
        float hf = __bfloat162float(hb);
        float lf = x - hf;
        g_xb[(size_t)row * 512 + lane + 32 * t] = hb;
        sq += x * x;
        h2s += hf * hf;
        l2s += lf * lf;
    }
#pragma unroll
    for (int off = 16; off; off >>= 1) {
        sq  += __shfl_xor_sync(0xffffffffu, sq, off);
        h2s += __shfl_xor_sync(0xffffffffu, h2s, off);
        l2s += __shfl_xor_sync(0xffffffffu, l2s, off);
    }
    if (lane == 0) {
        g_sq[row] = sq;
        float hn = sqrtf(h2s), ln = sqrtf(l2s);
        g_hin[row] = hn;
        g_lon[row] = ln;
        atomicMax(&g_HmaxBits, __float_as_int(hn));
        atomicMax(&g_LmaxBits, __float_as_int(ln));
    }
}

// ---------------- kernel 1: triangular HMMA gram-light (hi.hi, K=512) ----------------
// fp16 epilogue (direct + smem-transposed stores); diagonal poisoned inline.
#define TM 128
#define TN 128
#define KB 64
#define NCHUNK 8
#define NS 3
#define A_BYTES (TM * 128)
#define B_BYTES (TN * 128)
#define STAGE_BYTES (A_BYTES + B_BYTES)
#define SM_SQC 0
#define SM_SQR 512
#define SM_TILE0 1024
#define SMEM_GEMM (SM_TILE0 + NS * STAGE_BYTES)
#define TRANS_STRIDE 136

__device__ __forceinline__ int tri_cum(int I) { return 64 * I - (I * (I - 1)) / 2; }

__global__ __launch_bounds__(256, 2) void gram_store_tri() {
    extern __shared__ char smem[];
    const uint32_t sb = smem_u32(smem);
    float* sSqC = (float*)(smem + SM_SQC);
    float* sSqR = (float*)(smem + SM_SQR);

    const int tid = threadIdx.x;
    const int lane = tid & 31, wid = tid >> 5;
    const int warp_m = wid & 3, warp_n = wid >> 2;   // 4 x 2

    const int t = blockIdx.x;
    int I = (int)((129.0 - sqrt(129.0 * 129.0 - 8.0 * (double)t)) * 0.5);
    while (tri_cum(I + 1) <= t) I++;
    while (tri_cum(I) > t) I--;
    const int J = I + (t - tri_cum(I));
    const int row0 = I * TM;
    const int col0 = J * TN;
    const bool diag = (I == J);

    if (tid < 128) {
        sSqC[tid] = g_sq[col0 + tid];
        sSqR[tid] = g_sq[row0 + tid];
    }

    float acc[2][8][4];
#pragma unroll
    for (int mf = 0; mf < 2; mf++)
#pragma unroll
        for (int nf = 0; nf < 8; nf++)
#pragma unroll
            for (int e = 0; e < 4; e++) acc[mf][nf][e] = 0.f;

    const int lm_r = lane & 15;
    const int lm_k = (lane >> 4) * 8;

    const __nv_bfloat16* gXr = g_xb + (size_t)row0 * 512;
    const __nv_bfloat16* gXc = g_xb + (size_t)col0 * 512;

#define STAGE_CHUNK(cc)                                                                 \
    do {                                                                                \
        const int _st = (cc) % NS;                                                      \
        const uint32_t _sa = sb + SM_TILE0 + _st * STAGE_BYTES;                         \
        const uint32_t _sb2 = _sa + A_BYTES;                                            \
        const __nv_bfloat16* _gA = gXr + (cc) * KB;                                     \
        const __nv_bfloat16* _gB = gXc + (cc) * KB;                                     \
        _Pragma("unroll")                                                               \
        for (int _it = 0; _it < 4; _it++) {                                             \
            int _e = tid + _it * 256, _r = _e >> 3, _s = _e & 7;                        \
            cp_async16(_sa + SWZ(_r * 128 + _s * 16), _gA + (size_t)_r * 512 + _s * 8); \
            cp_async16(_sb2 + SWZ(_r * 128 + _s * 16), _gB + (size_t)_r * 512 + _s * 8);\
        }                                                                               \
        asm volatile("cp.async.commit_group;");                                         \
    } while (0)

    STAGE_CHUNK(0);
    STAGE_CHUNK(1);

    for (int c = 0; c < NCHUNK; c++) {
        if (c + 1 < NCHUNK) asm volatile("cp.async.wait_group 1;");
        else                asm volatile("cp.async.wait_group 0;");
        __syncthreads();
        if (c + 2 < NCHUNK) STAGE_CHUNK(c + 2);

        const uint32_t Ab = sb + SM_TILE0 + (c % NS) * STAGE_BYTES;
        const uint32_t Bb = Ab + A_BYTES;
#pragma unroll
        for (int ks = 0; ks < 4; ks++) {
            const int k0 = ks * 16;
            uint32_t a[2][4];
#pragma unroll
            for (int mf = 0; mf < 2; mf++) {
                int r = warp_m * 32 + mf * 16 + lm_r;
                ldmatrix_x4(a[mf], Ab + SWZ(r * 128 + (k0 + lm_k) * 2));
            }
            uint32_t b[4][4];
#pragma unroll
            for (int p = 0; p < 4; p++) {
                int n = warp_n * 64 + p * 16 + lm_r;
                ldmatrix_x4(b[p], Bb + SWZ(n * 128 + (k0 + lm_k) * 2));
            }
#pragma unroll
            for (int mf = 0; mf < 2; mf++)
#pragma unroll
                for (int nf = 0; nf < 8; nf++)
                    mma16816(acc[mf][nf], a[mf], b[nf >> 1][nf & 1], b[nf >> 1][(nf & 1) + 2]);
        }
    }

    __syncthreads();  // LDSM done; stage smem reusable for transpose
    __half* trans = (__half*)(smem + SM_TILE0);

#pragma unroll
    for (int mf = 0; mf < 2; mf++) {
        const int ra = warp_m * 32 + mf * 16 + (lane >> 2);
        const int rb = ra + 8;
        const float sqa = sSqR[ra], sqb = sSqR[rb];
#pragma unroll
        for (int nf = 0; nf < 8; nf++) {
            const int lc = warp_n * 64 + nf * 8 + (lane & 3) * 2;
            float c00 = sSqC[lc]     - 2.f * acc[mf][nf][0] - 1024.f;
            float c01 = sSqC[lc + 1] - 2.f * acc[mf][nf][1] - 1024.f;
            float c10 = sSqC[lc]     - 2.f * acc[mf][nf][2] - 1024.f;
            float c11 = sSqC[lc + 1] - 2.f * acc[mf][nf][3] - 1024.f;
            if (diag) {  // uniform branch: only 64/2080 CTAs pay this
                const int gra = row0 + ra, grb = row0 + rb;
                const int c0 = col0 + lc;
                if (c0 == gra)     c00 = 60000.f;
                if (c0 + 1 == gra) c01 = 60000.f;
                if (c0 == grb)     c10 = 60000.f;
                if (c0 + 1 == grb) c11 = 60000.f;
            }
            *(__half2*)&g_c[(size_t)(row0 + ra) * NPTS + col0 + lc] = __floats2half2_rn(c00, c01);
            *(__half2*)&g_c[(size_t)(row0 + rb) * NPTS + col0 + lc] = __floats2half2_rn(c10, c11);
            if (!diag) {
                trans[lc * TRANS_STRIDE + ra]       = __float2half_rn(sqa - 2.f * acc[mf][nf][0] - 1024.f);
                trans[(lc + 1) * TRANS_STRIDE + ra] = __float2half_rn(sqa - 2.f * acc[mf][nf][1] - 1024.f);
                trans[lc * TRANS_STRIDE + rb]       = __float2half_rn(sqb - 2.f * acc[mf][nf][2] - 1024.f);
                trans[(lc + 1) * TRANS_STRIDE + rb] = __float2half_rn(sqb - 2.f * acc[mf][nf][3] - 1024.f);
            }
        }
    }
    if (!diag) {
        __syncthreads();
#pragma unroll
        for (int it = 0; it < 8; it++) {
            int e = tid + it * 256;
            int r = e >> 4, s = e & 15;
            ((uint4*)(g_c + (size_t)(col0 + r) * NPTS + row0))[s] =
                ((const uint4*)(trans + r * TRANS_STRIDE))[s];
        }
    }
}

// ---------------- kernel 2: smem-cached scan + exact recheck ----------------
// Pass 1: stream the fp16 row (16 KB) into smem with packed hmin2 running min.
// Pass 2: enumerate c < th from smem into a queue; exact fp32 dots decide.
// Diagonal is poisoned in the gram epilogue. Occupancy 6 for memory-level
// parallelism in pass 1.
__global__ __launch_bounds__(256, 6) void scan_kernel(const float* __restrict__ xs) {
    __shared__ uint32_t sRow[4096];   // 16 KB: full fp16 row as half2 words
    __shared__ float sX[512];
    __shared__ float wMin[8];
    __shared__ float wBD[8];
    __shared__ int   wBJ[8];
    __shared__ int   qbuf[512];
    __shared__ int   qn;
    const int row = blockIdx.x;
    const int tid = threadIdx.x, lane = tid & 31, wid = tid >> 5;
    const uint4* crow = (const uint4*)(g_c + (size_t)row * NPTS);

    if (tid == 0) qn = 0;
    for (int i = tid; i < 512; i += 256) sX[i] = xs[(size_t)row * DIM + i];

    // pass 1: row -> smem, packed half2 min on the fly
    __half2 mn2 = __floats2half2_rn(60000.f, 60000.f);
#pragma unroll
    for (int it = 0; it < 4; it++) {
        uint4 v = crow[tid + it * 256];
        ((uint4*)sRow)[tid + it * 256] = v;
        mn2 = __hmin2(mn2, *(__half2*)&v.x);
        mn2 = __hmin2(mn2, *(__half2*)&v.y);
        mn2 = __hmin2(mn2, *(__half2*)&v.z);
        mn2 = __hmin2(mn2, *(__half2*)&v.w);
    }
    float m = fminf(__low2float(mn2), __high2float(mn2));
#pragma unroll
    for (int off = 16; off; off >>= 1) m = fminf(m, __shfl_xor_sync(0xffffffffu, m, off));
    if (lane == 0) wMin[wid] = m;
    __syncthreads();   // publishes sRow, sX, qn, wMin
    m = wMin[0];
#pragma unroll
    for (int w = 1; w < 8; w++) m = fminf(m, wMin[w]);

    const float Hmax = __int_as_float(g_HmaxBits);
    const float Lmax = __int_as_float(g_LmaxBits);
    const float th = m + 4.f * (g_hin[row] * Lmax + g_lon[row] * (Hmax + Lmax)) + 3.0f;
    const float sqi = g_sq[row];
    const __half2 th2 = __floats2half2_rn(th, th);

    // pass 2: candidate enumeration from smem
#pragma unroll 4
    for (int it = 0; it < 16; it++) {
        int w = tid + it * 256;
        __half2 x = *(__half2*)&sRow[w];
        __half2 lt = __hlt2(x, th2);   // 1.0 per half where x < th
        if (__low2float(lt) != 0.f) {
            int s = atomicAdd(&qn, 1);
            if (s < 512) qbuf[s] = 2 * w;
        }
        if (__high2float(lt) != 0.f) {
            int s = atomicAdd(&qn, 1);
            if (s < 512) qbuf[s] = 2 * w + 1;
        }
    }
    __syncthreads();

    float bd = 1e30f;
    int bj = NPTS;
    const int nq = (qn < 512) ? qn : 512;
    for (int q0 = wid; q0 < nq; q0 += 8) {
        int j = qbuf[q0];
        const float* xj = xs + (size_t)j * DIM;
        float s = 0.f;
#pragma unroll
        for (int tt = 0; tt < 16; tt++) s += sX[lane + 32 * tt] * xj[lane + 32 * tt];
#pragma unroll
        for (int off = 16; off; off >>= 1) s += __shfl_xor_sync(0xffffffffu, s, off);
        float d = sqi + g_sq[j] - 2.f * s;
        if (d < bd || (d == bd && j < bj)) { bd = d; bj = j; }
    }

    if (lane == 0) { wBD[wid] = bd; wBJ[wid] = bj; }
    __syncthreads();
    if (tid == 0) {
        float fb = wBD[0]; int fj = wBJ[0];
#pragma unroll
        for (int w = 1; w < 8; w++) {
            if (wBD[w] < fb || (wBD[w] == fb && wBJ[w] < fj)) { fb = wBD[w]; fj = wBJ[w]; }
        }
        g_closest[row] = fj;
    }
}

// ---------------- kernel Z1: Z1 = xs @ W1^T + b1  (64x64 tiles, f32x2) ----------------
__global__ __launch_bounds__(256, 2) void z1_gemm(
    const float* __restrict__ xs, const float* __restrict__ W1,
    const float* __restrict__ b1) {
    __shared__ float As[64][68];  // [k][r]
    __shared__ float Bs[64][68];  // [k][o]
    const int tid = threadIdx.x;
    const int tx = tid & 15, ty = tid >> 4;
    const int row0 = blockIdx.x * 64;

    u64 acc2[4][2];
#pragma unroll
    for (int m = 0; m < 4; m++) { acc2[m][0] = 0ull; acc2[m][1] = 0ull; }

    for (int kb = 0; kb < DIM; kb += 64) {
#pragma unroll
        for (int l = 0; l < 4; l++) {
            int e = tid + l * 256;
            int r = e >> 4, k4 = (e & 15) * 4;
            float4 va = *(const float4*)&xs[(size_t)(row0 + r) * DIM + kb + k4];
            As[k4 + 0][r] = va.x; As[k4 + 1][r] = va.y; As[k4 + 2][r] = va.z; As[k4 + 3][r] = va.w;
            float4 vb = *(const float4*)&W1[(size_t)r * DIM + kb + k4];
            Bs[k4 + 0][r] = vb.x; Bs[k4 + 1][r] = vb.y; Bs[k4 + 2][r] = vb.z; Bs[k4 + 3][r] = vb.w;
        }
        __syncthreads();
#pragma unroll
        for (int k = 0; k < 64; k++) {
            float4 a = *(const float4*)&As[k][tx * 4];
            const u64* bp = (const u64*)&Bs[k][ty * 4];
            u64 b0 = bp[0], b1v = bp[1];
            float ar[4] = {a.x, a.y, a.z, a.w};
#pragma unroll
            for (int m = 0; m < 4; m++) {
                u64 a2 = pack2(ar[m], ar[m]);
                acc2[m][0] = fma2(a2, b0, acc2[m][0]);
                acc2[m][1] = fma2(a2, b1v, acc2[m][1]);
            }
        }
        __syncthreads();
    }
#pragma unroll
    for (int m = 0; m < 4; m++)
#pragma unroll
        for (int n2 = 0; n2 < 2; n2++) {
            float2 v = unpack2(acc2[m][n2]);
            int o = ty * 4 + n2 * 2;
            g_Z1[(size_t)(row0 + tx * 4 + m) * 64 + o]     = v.x + __ldg(&b1[o]);
            g_Z1[(size_t)(row0 + tx * 4 + m) * 64 + o + 1] = v.y + __ldg(&b1[o + 1]);
        }
}

// ---------------- kernel Z2: Z2 = W2 @ relu(Z1) + b2 ----------------
__global__ __launch_bounds__(256, 4) void z2_kernel(
    const float* __restrict__ W2, const float* __restrict__ b2) {
    __shared__ float sW2t[64 * 32];
    __shared__ float sA[8][64];
    const int tid = threadIdx.x;
    for (int i = tid; i < 32 * 64; i += 256) {
        int o = i >> 6, k = i & 63;
        sW2t[k * 32 + o] = W2[i];
    }
    __syncthreads();
    const int warp = tid >> 5, lane = tid & 31;
    const int row = blockIdx.x * 8 + warp;
    float* a1 = sA[warp];
    a1[lane] = fmaxf(g_Z1[(size_t)row * 64 + lane], 0.f);
    a1[lane + 32] = fmaxf(g_Z1[(size_t)row * 64 + lane + 32], 0.f);
    __syncwarp();
    float z = __ldg(&b2[lane]);
#pragma unroll
    for (int k = 0; k < 64; k++) z += sW2t[k * 32 + lane] * a1[k];
    g_Z2[(size_t)row * 32 + lane] = z;
}

// ---------------- kernel PAIR: masked JVP encoder + decoder front ----------------
__global__ __launch_bounds__(256, 4) void pair_kernel(
    const float* __restrict__ W2, const float* __restrict__ b2,
    const float* __restrict__ W3, const float* __restrict__ b3,
    const float* __restrict__ D1, const float* __restrict__ d1,
    const float* __restrict__ D2, const float* __restrict__ d2,
    float* __restrict__ out) {
    __shared__ float sW2t[64 * 32];
    __shared__ float sW3t[32 * 32];
    __shared__ float sD1t[32 * 32];
    __shared__ float sD2t[32 * 64];
    __shared__ float sScr[8][160];
    const int tid = threadIdx.x;
    for (int i = tid; i < 32 * 64; i += 256) { int o = i >> 6, k = i & 63; sW2t[k * 32 + o] = W2[i]; }
    for (int i = tid; i < 32 * 32; i += 256) { int o = i >> 5, k = i & 31; sW3t[k * 32 + o] = W3[i]; sD1t[k * 32 + o] = D1[i]; }
    for (int i = tid; i < 64 * 32; i += 256) { int o = i >> 5, k = i & 31; sD2t[k * 64 + o] = D2[i]; }
    __syncthreads();

    const int warp = tid >> 5, lane = tid & 31;
    const int row = blockIdx.x * 8 + warp;
    float* sU  = sScr[warp];
    float* sU2 = sU + 64;
    float* sZ  = sU + 96;
    float* sH1 = sU + 128;

    const int j = g_closest[row];
#pragma unroll
    for (int h = 0; h < 2; h++) {
        int k = lane + 32 * h;
        float zi = g_Z1[(size_t)row * 64 + k];
        float zj = g_Z1[(size_t)j * 64 + k];
        sU[k] = (zj > 0.f) ? zi : 0.f;
    }
    __syncwarp();
    {
        float u2 = __ldg(&b2[lane]);
#pragma unroll
        for (int k = 0; k < 64; k++) u2 += sW2t[k * 32 + lane] * sU[k];
        float z2j = g_Z2[(size_t)j * 32 + lane];
        sU2[lane] = (z2j > 0.f) ? u2 : 0.f;
    }
    __syncwarp();
    {
        float z = __ldg(&b3[lane]);
#pragma unroll
        for (int k = 0; k < 32; k++) z += sW3t[k * 32 + lane] * sU2[k];
        sZ[lane] = z;
        out[(size_t)NPTS * DIM + (size_t)row * 32 + lane] = z;
    }
    __syncwarp();
    {
        float h = __ldg(&d1[lane]);
#pragma unroll
        for (int k = 0; k < 32; k++) h += sD1t[k * 32 + lane] * sZ[k];
        sH1[lane] = fmaxf(h, 0.f);
    }
    __syncwarp();
#pragma unroll
    for (int hh = 0; hh < 2; hh++) {
        int o = lane + 32 * hh;
        float h = __ldg(&d2[o]);
#pragma unroll
        for (int k = 0; k < 32; k++) h += sD2t[k * 64 + o] * sH1[k];
        g_h2[(size_t)row * 64 + o] = fmaxf(h, 0.f);
    }
}

// ---------------- kernel DEC: x_hat = h2 @ D3^T + d3  (f32x2 inner) ----------------
#define DEC_SMEM (2 * 64 * 132 * 4)
__global__ __launch_bounds__(256, 2) void dec_gemm(
    const float* __restrict__ D3, const float* __restrict__ d3,
    float* __restrict__ out) {
    extern __shared__ float ds[];
    float (*As)[132] = (float(*)[132])ds;
    float (*Bs)[132] = (float(*)[132])(ds + 64 * 132);
    const int tid = threadIdx.x;
    const int tx = tid & 15, ty = tid >> 4;
    const int row0 = blockIdx.x * 128;
    const int col0 = blockIdx.y * 128;

#pragma unroll
    for (int l = 0; l < 8; l++) {
        int e = tid + l * 256;
        int r = e >> 4, k4 = (e & 15) * 4;
        float4 va = *(const float4*)&g_h2[(size_t)(row0 + r) * 64 + k4];
        As[k4 + 0][r] = va.x; As[k4 + 1][r] = va.y; As[k4 + 2][r] = va.z; As[k4 + 3][r] = va.w;
        float4 vb = *(const float4*)&D3[(size_t)(col0 + r) * 64 + k4];
        Bs[k4 + 0][r] = vb.x; Bs[k4 + 1][r] = vb.y; Bs[k4 + 2][r] = vb.z; Bs[k4 + 3][r] = vb.w;
    }
    __syncthreads();

    u64 acc2[8][4];
#pragma unroll
    for (int m = 0; m < 8; m++)
#pragma unroll
        for (int n2 = 0; n2 < 4; n2++) acc2[m][n2] = 0ull;

#pragma unroll
    for (int k = 0; k < 64; k++) {
        float ar[8];
        float4 a0 = *(const float4*)&As[k][tx * 8];
        float4 a1 = *(const float4*)&As[k][tx * 8 + 4];
        ar[0] = a0.x; ar[1] = a0.y; ar[2] = a0.z; ar[3] = a0.w;
        ar[4] = a1.x; ar[5] = a1.y; ar[6] = a1.z; ar[7] = a1.w;
        const u64* bp = (const u64*)&Bs[k][ty * 8];
        u64 b2[4] = {bp[0], bp[1], bp[2], bp[3]};
#pragma unroll
        for (int m = 0; m < 8; m++) {
            u64 a2 = pack2(ar[m], ar[m]);
#pragma unroll
            for (int n2 = 0; n2 < 4; n2++) acc2[m][n2] = fma2(a2, b2[n2], acc2[m][n2]);
        }
    }

#pragma unroll
    for (int m = 0; m < 8; m++) {
        int r = row0 + tx * 8 + m;
#pragma unroll
        for (int n2 = 0; n2 < 4; n2++) {
            float2 v = unpack2(acc2[m][n2]);
            int cc = col0 + ty * 8 + n2 * 2;
            out[(size_t)r * DIM + cc]     = v.x + __ldg(&d3[cc]);
            out[(size_t)r * DIM + cc + 1] = v.y + __ldg(&d3[cc + 1]);
        }
    }
}

// ---------------- launch ----------------
extern "C" void kernel_launch(void* const* d_in, const int* in_sizes, int n_in,
                              void* d_out, int out_size) {
    const float* xs = (const float*)d_in[0];
    const float* W1 = (const float*)d_in[1];
    const float* b1 = (const float*)d_in[2];
    const float* W2 = (const float*)d_in[3];
    const float* b2 = (const float*)d_in[4];
    const float* W3 = (const float*)d_in[5];
    const float* b3 = (const float*)d_in[6];
    const float* D1 = (const float*)d_in[7];
    const float* d1 = (const float*)d_in[8];
    const float* D2 = (const float*)d_in[9];
    const float* d2 = (const float*)d_in[10];
    const float* D3 = (const float*)d_in[11];
    const float* d3 = (const float*)d_in[12];
    float* out = (float*)d_out;

    static cudaStream_t s_z = nullptr;
    static cudaEvent_t ev_g = nullptr, ev_z = nullptr;
    if (s_z == nullptr) {
        cudaStreamCreateWithFlags(&s_z, cudaStreamNonBlocking);
        cudaEventCreateWithFlags(&ev_g, cudaEventDisableTiming);
        cudaEventCreateWithFlags(&ev_z, cudaEventDisableTiming);
    }

    convert_norms_kernel<<<NPTS / 8, 256>>>(xs);

    cudaFuncSetAttribute(gram_store_tri, cudaFuncAttributeMaxDynamicSharedMemorySize, SMEM_GEMM);
    const int npairs = NBLK * (NBLK + 1) / 2;  // 2080
    gram_store_tri<<<npairs, 256, SMEM_GEMM>>>();
    cudaEventRecord(ev_g, 0);

    // z-path overlaps with the (memory-bound) scan, not the tensor-bound gram
    cudaStreamWaitEvent(s_z, ev_g, 0);
    z1_gemm<<<NPTS / 64, 256, 0, s_z>>>(xs, W1, b1);
    z2_kernel<<<NPTS / 8, 256, 0, s_z>>>(W2, b2);
    cudaEventRecord(ev_z, s_z);

    scan_kernel<<<NPTS, 256>>>(xs);

    cudaStreamWaitEvent(0, ev_z, 0);
    pair_kernel<<<NPTS / 8, 256>>>(W2, b2, W3, b3, D1, d1, D2, d2, out);

    cudaFuncSetAttribute(dec_gemm, cudaFuncAttributeMaxDynamicSharedMemorySize, DEC_SMEM);
    dim3 gdec(NPTS / 128, 4);
    dec_gemm<<<gdec, 256, DEC_SMEM>>>(D3, d3, out);
}